// round 1
// baseline (speedup 1.0000x reference)
#include <cuda_runtime.h>

#define NMAX 100000
#define EMAX 1600000
#define NODE_F 8
#define EDGE_F 2
#define HID 16
#define EDGE_IN 19   // g(1) + x[row](8) + x[col](8) + ea(2)
#define NODE_IN 11   // g(1) + x(8) + agg(2)

// ---- scratch (allocation-free rule: __device__ globals) ----
__device__ alignas(16) float d_xA[NMAX * NODE_F];
__device__ alignas(16) float d_xB[NMAX * NODE_F];
__device__ alignas(16) float d_eaA[EMAX * EDGE_F];
__device__ alignas(16) float d_eaB[EMAX * EDGE_F];
__device__ alignas(16) float d_agg[NMAX * EDGE_F];
__device__ float d_g;                 // current global feature (GLOB_F = 1)
__device__ float d_edge_acc[EDGE_F];  // sum of edge_emb over E
__device__ float d_node_acc[NODE_F];  // sum of node_emb over N

// ---------------------------------------------------------------------------
__global__ void init_kernel(const float* __restrict__ g_in, int n_agg) {
    int i = blockIdx.x * blockDim.x + threadIdx.x;
    if (i < n_agg) d_agg[i] = 0.f;
    if (i == 0) {
        d_g = g_in[0];
        d_edge_acc[0] = 0.f; d_edge_acc[1] = 0.f;
        #pragma unroll
        for (int k = 0; k < NODE_F; k++) d_node_acc[k] = 0.f;
    }
}

// ---------------------------------------------------------------------------
// Edge block: e_in = [g, x[row], x[col], ea] -> MLP(19->16 relu ->2)
// Scatter-adds result into d_agg[row], accumulates global edge sum.
__launch_bounds__(256)
__global__ void edge_kernel(const float* __restrict__ x,
                            const int*   __restrict__ ei,
                            const float* __restrict__ ea,
                            const float* __restrict__ W1, const float* __restrict__ b1,
                            const float* __restrict__ W2, const float* __restrict__ b2,
                            float* __restrict__ ea_out, int E, int writeOut)
{
    __shared__ float sW1[EDGE_IN * HID];
    __shared__ float sb1[HID];
    __shared__ float sW2[HID * EDGE_F];
    __shared__ float sb2[EDGE_F];
    __shared__ float sred[2][8];

    for (int i = threadIdx.x; i < EDGE_IN * HID; i += blockDim.x) sW1[i] = W1[i];
    if (threadIdx.x < HID)          sb1[threadIdx.x] = b1[threadIdx.x];
    if (threadIdx.x < HID * EDGE_F) sW2[threadIdx.x] = W2[threadIdx.x];
    if (threadIdx.x < EDGE_F)       sb2[threadIdx.x] = b2[threadIdx.x];
    __syncthreads();

    int e = blockIdx.x * blockDim.x + threadIdx.x;
    float o0 = 0.f, o1 = 0.f;
    if (e < E) {
        int r = ei[e];
        int c = ei[E + e];
        float4 xr0 = *reinterpret_cast<const float4*>(x + (size_t)r * NODE_F);
        float4 xr1 = *reinterpret_cast<const float4*>(x + (size_t)r * NODE_F + 4);
        float4 xc0 = *reinterpret_cast<const float4*>(x + (size_t)c * NODE_F);
        float4 xc1 = *reinterpret_cast<const float4*>(x + (size_t)c * NODE_F + 4);
        float2 eav = *reinterpret_cast<const float2*>(ea + (size_t)e * EDGE_F);

        float in[EDGE_IN];
        in[0]  = d_g;
        in[1]  = xr0.x; in[2]  = xr0.y; in[3]  = xr0.z; in[4]  = xr0.w;
        in[5]  = xr1.x; in[6]  = xr1.y; in[7]  = xr1.z; in[8]  = xr1.w;
        in[9]  = xc0.x; in[10] = xc0.y; in[11] = xc0.z; in[12] = xc0.w;
        in[13] = xc1.x; in[14] = xc1.y; in[15] = xc1.z; in[16] = xc1.w;
        in[17] = eav.x; in[18] = eav.y;

        float h[HID];
        #pragma unroll
        for (int j = 0; j < HID; j++) h[j] = sb1[j];
        #pragma unroll
        for (int i = 0; i < EDGE_IN; i++) {
            float v = in[i];
            #pragma unroll
            for (int j = 0; j < HID; j++) h[j] = fmaf(v, sW1[i * HID + j], h[j]);
        }
        o0 = sb2[0]; o1 = sb2[1];
        #pragma unroll
        for (int j = 0; j < HID; j++) {
            float hv = fmaxf(h[j], 0.f);
            o0 = fmaf(hv, sW2[j * EDGE_F + 0], o0);
            o1 = fmaf(hv, sW2[j * EDGE_F + 1], o1);
        }
        if (writeOut)
            *reinterpret_cast<float2*>(ea_out + (size_t)e * EDGE_F) = make_float2(o0, o1);
        atomicAdd(&d_agg[r * EDGE_F + 0], o0);
        atomicAdd(&d_agg[r * EDGE_F + 1], o1);
    }

    // block-level reduction of edge_emb sums (for global mean)
    float s0 = o0, s1 = o1;
    #pragma unroll
    for (int off = 16; off; off >>= 1) {
        s0 += __shfl_down_sync(0xffffffffu, s0, off);
        s1 += __shfl_down_sync(0xffffffffu, s1, off);
    }
    int warp = threadIdx.x >> 5, lane = threadIdx.x & 31;
    if (lane == 0) { sred[0][warp] = s0; sred[1][warp] = s1; }
    __syncthreads();
    if (threadIdx.x == 0) {
        float t0 = 0.f, t1 = 0.f;
        #pragma unroll
        for (int w = 0; w < 8; w++) { t0 += sred[0][w]; t1 += sred[1][w]; }
        atomicAdd(&d_edge_acc[0], t0);
        atomicAdd(&d_edge_acc[1], t1);
    }
}

// ---------------------------------------------------------------------------
// Node block: n_in = [g, x, agg] -> MLP(11->16 relu ->8); zeroes agg for next layer.
__launch_bounds__(256)
__global__ void node_kernel(const float* __restrict__ x,
                            const float* __restrict__ W1, const float* __restrict__ b1,
                            const float* __restrict__ W2, const float* __restrict__ b2,
                            float* __restrict__ x_out, int N)
{
    __shared__ float sW1[NODE_IN * HID];
    __shared__ float sb1[HID];
    __shared__ float sW2[HID * NODE_F];
    __shared__ float sb2[NODE_F];
    __shared__ float sred[NODE_F][8];

    for (int i = threadIdx.x; i < NODE_IN * HID; i += blockDim.x) sW1[i] = W1[i];
    if (threadIdx.x < HID)          sb1[threadIdx.x] = b1[threadIdx.x];
    if (threadIdx.x < HID * NODE_F) sW2[threadIdx.x] = W2[threadIdx.x];
    if (threadIdx.x < NODE_F)       sb2[threadIdx.x] = b2[threadIdx.x];
    __syncthreads();

    int n = blockIdx.x * blockDim.x + threadIdx.x;
    float out[NODE_F];
    #pragma unroll
    for (int k = 0; k < NODE_F; k++) out[k] = 0.f;

    if (n < N) {
        float4 xa = *reinterpret_cast<const float4*>(x + (size_t)n * NODE_F);
        float4 xb = *reinterpret_cast<const float4*>(x + (size_t)n * NODE_F + 4);
        float a0 = d_agg[n * EDGE_F + 0];
        float a1 = d_agg[n * EDGE_F + 1];
        d_agg[n * EDGE_F + 0] = 0.f;   // self-clean for the next layer / next replay
        d_agg[n * EDGE_F + 1] = 0.f;

        float in[NODE_IN];
        in[0] = d_g;
        in[1] = xa.x; in[2] = xa.y; in[3] = xa.z; in[4] = xa.w;
        in[5] = xb.x; in[6] = xb.y; in[7] = xb.z; in[8] = xb.w;
        in[9] = a0;   in[10] = a1;

        float h[HID];
        #pragma unroll
        for (int j = 0; j < HID; j++) h[j] = sb1[j];
        #pragma unroll
        for (int i = 0; i < NODE_IN; i++) {
            float v = in[i];
            #pragma unroll
            for (int j = 0; j < HID; j++) h[j] = fmaf(v, sW1[i * HID + j], h[j]);
        }
        #pragma unroll
        for (int k = 0; k < NODE_F; k++) out[k] = sb2[k];
        #pragma unroll
        for (int j = 0; j < HID; j++) {
            float hv = fmaxf(h[j], 0.f);
            #pragma unroll
            for (int k = 0; k < NODE_F; k++)
                out[k] = fmaf(hv, sW2[j * NODE_F + k], out[k]);
        }
        *reinterpret_cast<float4*>(x_out + (size_t)n * NODE_F)     = make_float4(out[0], out[1], out[2], out[3]);
        *reinterpret_cast<float4*>(x_out + (size_t)n * NODE_F + 4) = make_float4(out[4], out[5], out[6], out[7]);
    }

    // block-level reduction of node_emb sums (for global mean)
    int warp = threadIdx.x >> 5, lane = threadIdx.x & 31;
    #pragma unroll
    for (int k = 0; k < NODE_F; k++) {
        float s = out[k];
        #pragma unroll
        for (int off = 16; off; off >>= 1)
            s += __shfl_down_sync(0xffffffffu, s, off);
        if (lane == 0) sred[k][warp] = s;
    }
    __syncthreads();
    if (threadIdx.x < NODE_F) {
        float t = 0.f;
        #pragma unroll
        for (int w = 0; w < 8; w++) t += sred[threadIdx.x][w];
        atomicAdd(&d_node_acc[threadIdx.x], t);
    }
}

// ---------------------------------------------------------------------------
// Global block: [node_mean(8), edge_mean(2), g(1)] -> MLP(11->16 relu ->1)
// One warp; also zeroes the accumulators for the next layer / replay.
__global__ void glob_kernel(const float* __restrict__ W1, const float* __restrict__ b1,
                            const float* __restrict__ W2, const float* __restrict__ b2,
                            float invE, float invN)
{
    int t = threadIdx.x;
    float h = 0.f;
    if (t < HID) {
        h = b1[t];
        #pragma unroll
        for (int i = 0; i < NODE_F; i++)
            h = fmaf(d_node_acc[i] * invN, W1[i * HID + t], h);
        h = fmaf(d_edge_acc[0] * invE, W1[8 * HID + t], h);
        h = fmaf(d_edge_acc[1] * invE, W1[9 * HID + t], h);
        h = fmaf(d_g,                  W1[10 * HID + t], h);
        h = fmaxf(h, 0.f);
        h *= W2[t];              // glob_W2 is [16,1]
    }
    #pragma unroll
    for (int off = 16; off; off >>= 1)
        h += __shfl_down_sync(0xffffffffu, h, off);
    if (t == 0) {
        d_g = h + b2[0];
        d_edge_acc[0] = 0.f; d_edge_acc[1] = 0.f;
        #pragma unroll
        for (int i = 0; i < NODE_F; i++) d_node_acc[i] = 0.f;
    }
}

// ---------------------------------------------------------------------------
extern "C" void kernel_launch(void* const* d_in, const int* in_sizes, int n_in,
                              void* d_out, int out_size)
{
    const float* x0  = (const float*)d_in[0];
    const int*   ei  = (const int*)  d_in[1];
    const float* ea0 = (const float*)d_in[2];
    const float* g0  = (const float*)d_in[3];
    const float* eW1 = (const float*)d_in[4];
    const float* eb1 = (const float*)d_in[5];
    const float* eW2 = (const float*)d_in[6];
    const float* eb2 = (const float*)d_in[7];
    const float* nW1 = (const float*)d_in[8];
    const float* nb1 = (const float*)d_in[9];
    const float* nW2 = (const float*)d_in[10];
    const float* nb2 = (const float*)d_in[11];
    const float* gW1 = (const float*)d_in[12];
    const float* gb1 = (const float*)d_in[13];
    const float* gW2 = (const float*)d_in[14];
    const float* gb2 = (const float*)d_in[15];

    const int N = in_sizes[0] / NODE_F;
    const int E = in_sizes[2] / EDGE_F;
    float* out = (float*)d_out;

    float *xA, *xB, *eaA, *eaB;
    cudaGetSymbolAddress((void**)&xA,  d_xA);
    cudaGetSymbolAddress((void**)&xB,  d_xB);
    cudaGetSymbolAddress((void**)&eaA, d_eaA);
    cudaGetSymbolAddress((void**)&eaB, d_eaB);

    init_kernel<<<(N * EDGE_F + 255) / 256, 256>>>(g0, N * EDGE_F);

    const float* xin[3]  = {x0, xA, xB};
    float*       xout[3] = {xA, xB, out};
    const float* eain[3] = {ea0, eaA, eaB};
    float*       eaout[3]= {eaA, eaB, eaA};  // layer-2 output unused (writeOut=0)

    const float invE = 1.0f / (float)E;
    const float invN = 1.0f / (float)N;

    for (int l = 0; l < 3; l++) {
        edge_kernel<<<(E + 255) / 256, 256>>>(
            xin[l], ei, eain[l],
            eW1 + l * EDGE_IN * HID, eb1 + l * HID,
            eW2 + l * HID * EDGE_F,  eb2 + l * EDGE_F,
            eaout[l], E, (l < 2) ? 1 : 0);

        node_kernel<<<(N + 255) / 256, 256>>>(
            xin[l],
            nW1 + l * NODE_IN * HID, nb1 + l * HID,
            nW2 + l * HID * NODE_F,  nb2 + l * NODE_F,
            xout[l], N);

        glob_kernel<<<1, 32>>>(
            gW1 + l * NODE_IN * HID, gb1 + l * HID,
            gW2 + l * HID,           gb2 + l,
            invE, invN);
    }
}

// round 2
// speedup vs baseline: 1.0235x; 1.0235x over previous
#include <cuda_runtime.h>

#define NODE_F 8
#define EDGE_F 2
#define HID 16
#define NMAX 100000
#define EMAX 1600000

// ---- scratch (__device__ globals per allocation-free rule) ----
__device__ alignas(16) float d_xA[NMAX * NODE_F];
__device__ alignas(16) float d_xB[NMAX * NODE_F];
__device__ alignas(16) float d_ea[EMAX * EDGE_F];
__device__ alignas(16) float d_p[NMAX * HID];     // A_l . x[n]
__device__ alignas(16) float d_q[NMAX * HID];     // B_l . x[n]
__device__ alignas(16) float d_agg[NMAX * EDGE_F];   // zero-init, self-cleaning
__device__ float d_g;
__device__ float d_eacc[EDGE_F];   // zero-init, self-cleaning
__device__ float d_nacc[NODE_F];   // zero-init, self-cleaning
__device__ float d_ebias[2][HID];  // b1_e + g*W1_e[row_g], double buffered
__device__ float d_nbias[2][HID];
__device__ unsigned d_count;       // zero-init, self-cleaning

// ---------------------------------------------------------------------------
// init: g and layer-0 folded biases
__global__ void init_kernel(const float* __restrict__ g_in,
                            const float* __restrict__ eW1r0, const float* __restrict__ eb1,
                            const float* __restrict__ nW1r0, const float* __restrict__ nb1,
                            float* __restrict__ ebias0, float* __restrict__ nbias0)
{
    int t = threadIdx.x;
    float g = g_in[0];
    if (t < HID) {
        ebias0[t] = eb1[t] + g * eW1r0[t];
        nbias0[t] = nb1[t] + g * nW1r0[t];
    }
    if (t == 0) d_g = g;
}

// ---------------------------------------------------------------------------
// layer-0 p/q precompute from external x
__global__ __launch_bounds__(256)
void pre_kernel(const float* __restrict__ x,
                const float* __restrict__ A, const float* __restrict__ B, int N)
{
    __shared__ float sA[NODE_F * HID], sB[NODE_F * HID];
    for (int i = threadIdx.x; i < NODE_F * HID; i += blockDim.x) { sA[i] = A[i]; sB[i] = B[i]; }
    __syncthreads();
    int n = blockIdx.x * blockDim.x + threadIdx.x;
    if (n >= N) return;
    float xv[NODE_F];
    *reinterpret_cast<float4*>(xv)     = *reinterpret_cast<const float4*>(x + (size_t)n * NODE_F);
    *reinterpret_cast<float4*>(xv + 4) = *reinterpret_cast<const float4*>(x + (size_t)n * NODE_F + 4);
    float pv[HID], qv[HID];
    #pragma unroll
    for (int j = 0; j < HID; j++) { pv[j] = 0.f; qv[j] = 0.f; }
    #pragma unroll
    for (int k = 0; k < NODE_F; k++) {
        float v = xv[k];
        #pragma unroll
        for (int j = 0; j < HID; j++) {
            pv[j] = fmaf(v, sA[k * HID + j], pv[j]);
            qv[j] = fmaf(v, sB[k * HID + j], qv[j]);
        }
    }
    float4* pd = reinterpret_cast<float4*>(d_p + (size_t)n * HID);
    float4* qd = reinterpret_cast<float4*>(d_q + (size_t)n * HID);
    #pragma unroll
    for (int v = 0; v < 4; v++) {
        pd[v] = reinterpret_cast<float4*>(pv)[v];
        qd[v] = reinterpret_cast<float4*>(qv)[v];
    }
}

// ---------------------------------------------------------------------------
// Edge block: h = ebias + p[r] + q[c] + C.ea ; relu ; out = W2.h + b2
// Scatter-add to d_agg[r] via vector red; optional edge-sum reduction.
template<bool WRITE_EA, bool REDUCE>
__global__ __launch_bounds__(256)
void edge_kernel(const int* __restrict__ ei, const float* __restrict__ ea,
                 const float* __restrict__ C, const float* __restrict__ W2,
                 const float* __restrict__ b2, const float* __restrict__ ebias,
                 float* __restrict__ ea_out, int E)
{
    __shared__ float sC[2 * HID], sW2[HID * 2], sEb[HID], sB2[2];
    __shared__ float sred[2][8];
    int tx = threadIdx.x;
    if (tx < 32)       sC[tx] = C[tx];
    else if (tx < 64)  sW2[tx - 32] = W2[tx - 32];
    else if (tx < 80)  sEb[tx - 64] = ebias[tx - 64];
    else if (tx < 82)  sB2[tx - 80] = b2[tx - 80];
    __syncthreads();

    float acc0 = 0.f, acc1 = 0.f;
    int e = blockIdx.x * 512 + tx;
    #pragma unroll
    for (int it = 0; it < 2; it++, e += 256) {
        if (e < E) {
            int r = ei[e];
            int c = ei[E + e];
            const float4* pp = reinterpret_cast<const float4*>(d_p + (size_t)r * HID);
            const float4* qq = reinterpret_cast<const float4*>(d_q + (size_t)c * HID);
            float pv[HID], qv[HID];
            #pragma unroll
            for (int v = 0; v < 4; v++) {
                reinterpret_cast<float4*>(pv)[v] = pp[v];
                reinterpret_cast<float4*>(qv)[v] = qq[v];
            }
            float2 eav = *reinterpret_cast<const float2*>(ea + (size_t)e * EDGE_F);

            float o0 = sB2[0], o1 = sB2[1];
            #pragma unroll
            for (int j = 0; j < HID; j++) {
                float h = sEb[j] + pv[j] + qv[j];
                h = fmaf(eav.x, sC[j], h);
                h = fmaf(eav.y, sC[HID + j], h);
                h = fmaxf(h, 0.f);
                o0 = fmaf(h, sW2[2 * j], o0);
                o1 = fmaf(h, sW2[2 * j + 1], o1);
            }
            if (WRITE_EA)
                *reinterpret_cast<float2*>(ea_out + (size_t)e * EDGE_F) = make_float2(o0, o1);
            float* dst = &d_agg[(size_t)r * EDGE_F];
            asm volatile("red.global.add.v2.f32 [%0], {%1, %2};"
                         :: "l"(dst), "f"(o0), "f"(o1) : "memory");
            if (REDUCE) { acc0 += o0; acc1 += o1; }
        }
    }

    if (REDUCE) {
        #pragma unroll
        for (int off = 16; off; off >>= 1) {
            acc0 += __shfl_down_sync(0xffffffffu, acc0, off);
            acc1 += __shfl_down_sync(0xffffffffu, acc1, off);
        }
        int warp = tx >> 5, lane = tx & 31;
        if (lane == 0) { sred[0][warp] = acc0; sred[1][warp] = acc1; }
        __syncthreads();
        if (tx == 0) {
            float t0 = 0.f, t1 = 0.f;
            #pragma unroll
            for (int w = 0; w < 8; w++) { t0 += sred[0][w]; t1 += sred[1][w]; }
            atomicAdd(&d_eacc[0], t0);
            atomicAdd(&d_eacc[1], t1);
        }
    }
}

// ---------------------------------------------------------------------------
// Node block: n_in = [g, x, agg] -> MLP(11->16 relu ->8).
// FUSE: also computes next-layer p/q per node, block-reduces node sums,
// and the LAST block runs the global MLP + folds next-layer biases.
template<bool FUSE>
__global__ __launch_bounds__(256)
void node_kernel(const float* __restrict__ x,
                 const float* __restrict__ W1,      // rows 1..10 (160 floats)
                 const float* __restrict__ nbias,
                 const float* __restrict__ W2, const float* __restrict__ b2,
                 float* __restrict__ x_out,
                 const float* __restrict__ An, const float* __restrict__ Bn, // next edge A,B
                 const float* __restrict__ gW1, const float* __restrict__ gb1,
                 const float* __restrict__ gW2, const float* __restrict__ gb2,
                 const float* __restrict__ eW1r0n, const float* __restrict__ eb1n,
                 const float* __restrict__ nW1r0n, const float* __restrict__ nb1n,
                 float* __restrict__ ebias_out, float* __restrict__ nbias_out,
                 float invE, float invN, int N)
{
    __shared__ float sW1[10 * HID], sNb[HID], sW2n[HID * NODE_F], sB2[NODE_F];
    __shared__ float sA[NODE_F * HID], sBm[NODE_F * HID];
    __shared__ float sred[NODE_F][8];
    __shared__ bool  isLast;
    int tx = threadIdx.x;

    for (int i = tx; i < 10 * HID; i += 256) sW1[i] = W1[i];
    for (int i = tx; i < HID * NODE_F; i += 256) sW2n[i] = W2[i];
    if (tx < HID)    sNb[tx] = nbias[tx];
    if (tx < NODE_F) sB2[tx] = b2[tx];
    if (FUSE) {
        for (int i = tx; i < NODE_F * HID; i += 256) { sA[i] = An[i]; sBm[i] = Bn[i]; }
    }
    __syncthreads();

    int n = blockIdx.x * blockDim.x + tx;
    float out[NODE_F];
    #pragma unroll
    for (int k = 0; k < NODE_F; k++) out[k] = 0.f;

    if (n < N) {
        float xv[NODE_F];
        *reinterpret_cast<float4*>(xv)     = *reinterpret_cast<const float4*>(x + (size_t)n * NODE_F);
        *reinterpret_cast<float4*>(xv + 4) = *reinterpret_cast<const float4*>(x + (size_t)n * NODE_F + 4);
        float a0 = d_agg[(size_t)n * EDGE_F + 0];
        float a1 = d_agg[(size_t)n * EDGE_F + 1];
        d_agg[(size_t)n * EDGE_F + 0] = 0.f;   // self-clean
        d_agg[(size_t)n * EDGE_F + 1] = 0.f;

        float h[HID];
        #pragma unroll
        for (int j = 0; j < HID; j++) h[j] = sNb[j];
        #pragma unroll
        for (int i = 0; i < NODE_F; i++) {
            float v = xv[i];
            #pragma unroll
            for (int j = 0; j < HID; j++) h[j] = fmaf(v, sW1[i * HID + j], h[j]);
        }
        #pragma unroll
        for (int j = 0; j < HID; j++) {
            h[j] = fmaf(a0, sW1[8 * HID + j], h[j]);
            h[j] = fmaf(a1, sW1[9 * HID + j], h[j]);
        }
        #pragma unroll
        for (int k = 0; k < NODE_F; k++) out[k] = sB2[k];
        #pragma unroll
        for (int j = 0; j < HID; j++) {
            float hv = fmaxf(h[j], 0.f);
            #pragma unroll
            for (int k = 0; k < NODE_F; k++)
                out[k] = fmaf(hv, sW2n[j * NODE_F + k], out[k]);
        }
        *reinterpret_cast<float4*>(x_out + (size_t)n * NODE_F)     = *reinterpret_cast<float4*>(out);
        *reinterpret_cast<float4*>(x_out + (size_t)n * NODE_F + 4) = *reinterpret_cast<float4*>(out + 4);

        if (FUSE) {   // next-layer p/q from the fresh embedding
            float pv[HID], qv[HID];
            #pragma unroll
            for (int j = 0; j < HID; j++) { pv[j] = 0.f; qv[j] = 0.f; }
            #pragma unroll
            for (int k = 0; k < NODE_F; k++) {
                float v = out[k];
                #pragma unroll
                for (int j = 0; j < HID; j++) {
                    pv[j] = fmaf(v, sA[k * HID + j], pv[j]);
                    qv[j] = fmaf(v, sBm[k * HID + j], qv[j]);
                }
            }
            float4* pd = reinterpret_cast<float4*>(d_p + (size_t)n * HID);
            float4* qd = reinterpret_cast<float4*>(d_q + (size_t)n * HID);
            #pragma unroll
            for (int v = 0; v < 4; v++) {
                pd[v] = reinterpret_cast<float4*>(pv)[v];
                qd[v] = reinterpret_cast<float4*>(qv)[v];
            }
        }
    }

    if (FUSE) {
        // block reduction of node embedding sums
        int warp = tx >> 5, lane = tx & 31;
        #pragma unroll
        for (int k = 0; k < NODE_F; k++) {
            float s = out[k];
            #pragma unroll
            for (int off = 16; off; off >>= 1)
                s += __shfl_down_sync(0xffffffffu, s, off);
            if (lane == 0) sred[k][warp] = s;
        }
        __syncthreads();
        if (tx < NODE_F) {
            float t = 0.f;
            #pragma unroll
            for (int w = 0; w < 8; w++) t += sred[tx][w];
            atomicAdd(&d_nacc[tx], t);
            __threadfence();
        }
        __syncthreads();
        if (tx == 0) {
            unsigned t = atomicAdd(&d_count, 1u);
            isLast = (t == gridDim.x - 1);
        }
        __syncthreads();

        if (isLast) {
            __threadfence();
            if (tx < 32) {
                float gv = d_g;
                float h = 0.f;
                if (tx < HID) {
                    h = gb1[tx];
                    #pragma unroll
                    for (int i = 0; i < NODE_F; i++)
                        h = fmaf(d_nacc[i] * invN, gW1[i * HID + tx], h);
                    h = fmaf(d_eacc[0] * invE, gW1[8 * HID + tx], h);
                    h = fmaf(d_eacc[1] * invE, gW1[9 * HID + tx], h);
                    h = fmaf(gv, gW1[10 * HID + tx], h);
                    h = fmaxf(h, 0.f) * gW2[tx];
                }
                #pragma unroll
                for (int off = 16; off; off >>= 1)
                    h += __shfl_down_sync(0xffffffffu, h, off);
                float gn = __shfl_sync(0xffffffffu, h, 0) + gb2[0];
                if (tx == 0) d_g = gn;
                if (tx < HID) {
                    ebias_out[tx] = eb1n[tx] + gn * eW1r0n[tx];
                    nbias_out[tx] = nb1n[tx] + gn * nW1r0n[tx];
                }
                if (tx < NODE_F) d_nacc[tx] = 0.f;   // self-clean
                if (tx < EDGE_F) d_eacc[tx] = 0.f;
                if (tx == 0)     d_count = 0u;
            }
        }
    }
}

// ---------------------------------------------------------------------------
extern "C" void kernel_launch(void* const* d_in, const int* in_sizes, int n_in,
                              void* d_out, int out_size)
{
    const float* x0  = (const float*)d_in[0];
    const int*   ei  = (const int*)  d_in[1];
    const float* ea0 = (const float*)d_in[2];
    const float* g0  = (const float*)d_in[3];
    const float* eW1 = (const float*)d_in[4];
    const float* eb1 = (const float*)d_in[5];
    const float* eW2 = (const float*)d_in[6];
    const float* eb2 = (const float*)d_in[7];
    const float* nW1 = (const float*)d_in[8];
    const float* nb1 = (const float*)d_in[9];
    const float* nW2 = (const float*)d_in[10];
    const float* nb2 = (const float*)d_in[11];
    const float* gW1 = (const float*)d_in[12];
    const float* gb1 = (const float*)d_in[13];
    const float* gW2 = (const float*)d_in[14];
    const float* gb2 = (const float*)d_in[15];

    const int N = in_sizes[0] / NODE_F;
    const int E = in_sizes[2] / EDGE_F;
    float* out = (float*)d_out;

    float *xA, *xB, *ea, *pEb, *pNb;
    cudaGetSymbolAddress((void**)&xA,  d_xA);
    cudaGetSymbolAddress((void**)&xB,  d_xB);
    cudaGetSymbolAddress((void**)&ea,  d_ea);
    cudaGetSymbolAddress((void**)&pEb, d_ebias);
    cudaGetSymbolAddress((void**)&pNb, d_nbias);

    const float invE = 1.0f / (float)E;
    const float invN = 1.0f / (float)N;

    // layer strides
    const int EW1S = 19 * HID, NW1S = 11 * HID, GW1S = 11 * HID;

    init_kernel<<<1, 32>>>(g0, eW1, eb1, nW1, nb1, pEb, pNb);
    pre_kernel<<<(N + 255) / 256, 256>>>(x0, eW1 + HID, eW1 + 9 * HID, N);

    const float* xin[3]  = {x0, xA, xB};
    float*       xout[3] = {xA, xB, out};
    const float* eain[3] = {ea0, ea, ea};

    const int eblocks = (E + 511) / 512;
    const int nblocks = (N + 255) / 256;

    for (int l = 0; l < 3; l++) {
        const float* C    = eW1 + l * EW1S + 17 * HID;
        const float* W2e  = eW2 + l * HID * EDGE_F;
        const float* b2e  = eb2 + l * EDGE_F;
        const float* eb_l = pEb + (l & 1) * HID;

        if (l < 2)
            edge_kernel<true, true><<<eblocks, 256>>>(ei, eain[l], C, W2e, b2e, eb_l, ea, E);
        else
            edge_kernel<false, false><<<eblocks, 256>>>(ei, eain[l], C, W2e, b2e, eb_l, ea, E);

        const float* W1n  = nW1 + l * NW1S + HID;      // rows 1..10
        const float* nb_l = pNb + (l & 1) * HID;
        const float* W2n  = nW2 + l * HID * NODE_F;
        const float* b2n  = nb2 + l * NODE_F;

        if (l < 2) {
            node_kernel<true><<<nblocks, 256>>>(
                xin[l], W1n, nb_l, W2n, b2n, xout[l],
                eW1 + (l + 1) * EW1S + HID, eW1 + (l + 1) * EW1S + 9 * HID,
                gW1 + l * GW1S, gb1 + l * HID, gW2 + l * HID, gb2 + l,
                eW1 + (l + 1) * EW1S, eb1 + (l + 1) * HID,
                nW1 + (l + 1) * NW1S, nb1 + (l + 1) * HID,
                pEb + ((l + 1) & 1) * HID, pNb + ((l + 1) & 1) * HID,
                invE, invN, N);
        } else {
            node_kernel<false><<<nblocks, 256>>>(
                xin[l], W1n, nb_l, W2n, b2n, xout[l],
                nullptr, nullptr, nullptr, nullptr, nullptr, nullptr,
                nullptr, nullptr, nullptr, nullptr, nullptr, nullptr,
                invE, invN, N);
        }
    }
}

// round 3
// speedup vs baseline: 1.2324x; 1.2041x over previous
#include <cuda_runtime.h>

#define NODE_F 8
#define EDGE_F 2
#define HID 16
#define NMAX 100000
#define EMAX 1600000

// ---- scratch (__device__ globals per allocation-free rule) ----
__device__ alignas(16) float d_xA[NMAX * NODE_F];
__device__ alignas(16) float d_xB[NMAX * NODE_F];
__device__ alignas(16) float d_ea[EMAX * EDGE_F];
__device__ alignas(16) float d_p[NMAX * HID];     // A_l . x[n]  (64B row, line-aligned)
__device__ alignas(16) float d_q[NMAX * HID];     // B_l . x[n]
__device__ alignas(16) float d_agg[NMAX * EDGE_F];   // zero-init, self-cleaning
__device__ float d_g;
__device__ float d_eacc[EDGE_F];   // zero-init, self-cleaning
__device__ float d_nacc[NODE_F];   // zero-init, self-cleaning
__device__ float d_ebias[2][HID];  // b1_e + g*W1_e[g-row], double buffered
__device__ float d_nbias[2][HID];
__device__ unsigned d_count;       // zero-init, self-cleaning

// ---------------------------------------------------------------------------
__global__ void init_kernel(const float* __restrict__ g_in,
                            const float* __restrict__ eW1r0, const float* __restrict__ eb1,
                            const float* __restrict__ nW1r0, const float* __restrict__ nb1,
                            float* __restrict__ ebias0, float* __restrict__ nbias0)
{
    int t = threadIdx.x;
    float g = g_in[0];
    if (t < HID) {
        ebias0[t] = eb1[t] + g * eW1r0[t];
        nbias0[t] = nb1[t] + g * nW1r0[t];
    }
    if (t == 0) d_g = g;
}

// ---------------------------------------------------------------------------
// layer-0 p/q precompute from external x
__global__ __launch_bounds__(256)
void pre_kernel(const float* __restrict__ x,
                const float* __restrict__ A, const float* __restrict__ B, int N)
{
    __shared__ float sA[NODE_F * HID], sB[NODE_F * HID];
    for (int i = threadIdx.x; i < NODE_F * HID; i += blockDim.x) { sA[i] = A[i]; sB[i] = B[i]; }
    __syncthreads();
    int n = blockIdx.x * blockDim.x + threadIdx.x;
    if (n >= N) return;
    float xv[NODE_F];
    *reinterpret_cast<float4*>(xv)     = *reinterpret_cast<const float4*>(x + (size_t)n * NODE_F);
    *reinterpret_cast<float4*>(xv + 4) = *reinterpret_cast<const float4*>(x + (size_t)n * NODE_F + 4);
    float pv[HID], qv[HID];
    #pragma unroll
    for (int j = 0; j < HID; j++) { pv[j] = 0.f; qv[j] = 0.f; }
    #pragma unroll
    for (int k = 0; k < NODE_F; k++) {
        float v = xv[k];
        #pragma unroll
        for (int j = 0; j < HID; j++) {
            pv[j] = fmaf(v, sA[k * HID + j], pv[j]);
            qv[j] = fmaf(v, sB[k * HID + j], qv[j]);
        }
    }
    float4* pd = reinterpret_cast<float4*>(d_p + (size_t)n * HID);
    float4* qd = reinterpret_cast<float4*>(d_q + (size_t)n * HID);
    #pragma unroll
    for (int v = 0; v < 4; v++) {
        pd[v] = reinterpret_cast<float4*>(pv)[v];
        qd[v] = reinterpret_cast<float4*>(qv)[v];
    }
}

// ---------------------------------------------------------------------------
// Edge block, 4 lanes per edge: one LDG.128 per lane covers 1/4 of p[r] (q[c]).
// A warp's gather instruction touches only 8 lines (8 edges) instead of 32.
// h_j = ebias_j + p_j + q_j + C.ea ; relu ; o = W2.h + b2 (cross-lane reduce).
#define ESTEPS 4   // edges per block = 64 * ESTEPS
template<bool WRITE_EA, bool REDUCE>
__global__ __launch_bounds__(256)
void edge_kernel(const int* __restrict__ ei, const float* __restrict__ ea,
                 const float* __restrict__ C, const float* __restrict__ W2,
                 const float* __restrict__ b2, const float* __restrict__ ebias,
                 float* __restrict__ ea_out, int E)
{
    __shared__ float sC[2 * HID], sW2[HID * 2], sEb[HID];
    __shared__ float sred[2][8];
    int tx = threadIdx.x;
    if (tx < 32)       sC[tx] = C[tx];
    else if (tx < 64)  sW2[tx - 32] = W2[tx - 32];
    else if (tx < 80)  sEb[tx - 64] = ebias[tx - 64];
    __syncthreads();

    const float B20 = __ldg(&b2[0]);
    const float B21 = __ldg(&b2[1]);

    const int sub   = tx & 3;         // lane within edge-group
    const int group = tx >> 2;        // 0..63 within block
    const int j0    = sub * 4;        // this lane's 4 hidden units
    float acc0 = 0.f, acc1 = 0.f;

    int e = blockIdx.x * (64 * ESTEPS) + group;
    #pragma unroll
    for (int s = 0; s < ESTEPS; s++, e += 64) {
        if (e < E) {
            int r = ei[e];            // 4 lanes share the address; warp: 8 ids, 1 line
            int c = ei[E + e];
            float4 pv = *reinterpret_cast<const float4*>(d_p + (size_t)r * HID + j0);
            float4 qv = *reinterpret_cast<const float4*>(d_q + (size_t)c * HID + j0);
            float2 eav = *reinterpret_cast<const float2*>(ea + (size_t)e * EDGE_F);

            float o0 = 0.f, o1 = 0.f;
            float hp[4] = {pv.x, pv.y, pv.z, pv.w};
            float hq[4] = {qv.x, qv.y, qv.z, qv.w};
            #pragma unroll
            for (int k = 0; k < 4; k++) {
                float h = sEb[j0 + k] + hp[k] + hq[k];
                h = fmaf(eav.x, sC[j0 + k], h);
                h = fmaf(eav.y, sC[HID + j0 + k], h);
                h = fmaxf(h, 0.f);
                o0 = fmaf(h, sW2[2 * (j0 + k)],     o0);
                o1 = fmaf(h, sW2[2 * (j0 + k) + 1], o1);
            }
            // reduce across the 4 sub-lanes
            o0 += __shfl_xor_sync(0xffffffffu, o0, 1);
            o1 += __shfl_xor_sync(0xffffffffu, o1, 1);
            o0 += __shfl_xor_sync(0xffffffffu, o0, 2);
            o1 += __shfl_xor_sync(0xffffffffu, o1, 2);

            if (sub == 0) {
                o0 += B20; o1 += B21;
                if (WRITE_EA)
                    *reinterpret_cast<float2*>(ea_out + (size_t)e * EDGE_F) = make_float2(o0, o1);
                float* dst = &d_agg[(size_t)r * EDGE_F];
                asm volatile("red.global.add.v2.f32 [%0], {%1, %2};"
                             :: "l"(dst), "f"(o0), "f"(o1) : "memory");
                if (REDUCE) { acc0 += o0; acc1 += o1; }
            }
        }
    }

    if (REDUCE) {
        #pragma unroll
        for (int off = 16; off; off >>= 1) {
            acc0 += __shfl_down_sync(0xffffffffu, acc0, off);
            acc1 += __shfl_down_sync(0xffffffffu, acc1, off);
        }
        int warp = tx >> 5, lane = tx & 31;
        if (lane == 0) { sred[0][warp] = acc0; sred[1][warp] = acc1; }
        __syncthreads();
        if (tx == 0) {
            float t0 = 0.f, t1 = 0.f;
            #pragma unroll
            for (int w = 0; w < 8; w++) { t0 += sred[0][w]; t1 += sred[1][w]; }
            atomicAdd(&d_eacc[0], t0);
            atomicAdd(&d_eacc[1], t1);
        }
    }
}

// ---------------------------------------------------------------------------
// Node block: n_in = [g, x, agg] -> MLP(11->16 relu ->8).
// FUSE: also computes next-layer p/q per node, block-reduces node sums,
// and the LAST block runs the global MLP + folds next-layer biases.
template<bool FUSE>
__global__ __launch_bounds__(256)
void node_kernel(const float* __restrict__ x,
                 const float* __restrict__ W1,      // rows 1..10 (160 floats)
                 const float* __restrict__ nbias,
                 const float* __restrict__ W2, const float* __restrict__ b2,
                 float* __restrict__ x_out,
                 const float* __restrict__ An, const float* __restrict__ Bn,
                 const float* __restrict__ gW1, const float* __restrict__ gb1,
                 const float* __restrict__ gW2, const float* __restrict__ gb2,
                 const float* __restrict__ eW1r0n, const float* __restrict__ eb1n,
                 const float* __restrict__ nW1r0n, const float* __restrict__ nb1n,
                 float* __restrict__ ebias_out, float* __restrict__ nbias_out,
                 float invE, float invN, int N)
{
    __shared__ float sW1[10 * HID], sNb[HID], sW2n[HID * NODE_F], sB2[NODE_F];
    __shared__ float sA[NODE_F * HID], sBm[NODE_F * HID];
    __shared__ float sred[NODE_F][8];
    __shared__ bool  isLast;
    int tx = threadIdx.x;

    for (int i = tx; i < 10 * HID; i += 256) sW1[i] = W1[i];
    for (int i = tx; i < HID * NODE_F; i += 256) sW2n[i] = W2[i];
    if (tx < HID)    sNb[tx] = nbias[tx];
    if (tx < NODE_F) sB2[tx] = b2[tx];
    if (FUSE) {
        for (int i = tx; i < NODE_F * HID; i += 256) { sA[i] = An[i]; sBm[i] = Bn[i]; }
    }
    __syncthreads();

    int n = blockIdx.x * blockDim.x + tx;
    float out[NODE_F];
    #pragma unroll
    for (int k = 0; k < NODE_F; k++) out[k] = 0.f;

    if (n < N) {
        float xv[NODE_F];
        *reinterpret_cast<float4*>(xv)     = *reinterpret_cast<const float4*>(x + (size_t)n * NODE_F);
        *reinterpret_cast<float4*>(xv + 4) = *reinterpret_cast<const float4*>(x + (size_t)n * NODE_F + 4);
        float2 av = *reinterpret_cast<float2*>(&d_agg[(size_t)n * EDGE_F]);
        *reinterpret_cast<float2*>(&d_agg[(size_t)n * EDGE_F]) = make_float2(0.f, 0.f); // self-clean

        float h[HID];
        #pragma unroll
        for (int j = 0; j < HID; j++) h[j] = sNb[j];
        #pragma unroll
        for (int i = 0; i < NODE_F; i++) {
            float v = xv[i];
            #pragma unroll
            for (int j = 0; j < HID; j++) h[j] = fmaf(v, sW1[i * HID + j], h[j]);
        }
        #pragma unroll
        for (int j = 0; j < HID; j++) {
            h[j] = fmaf(av.x, sW1[8 * HID + j], h[j]);
            h[j] = fmaf(av.y, sW1[9 * HID + j], h[j]);
        }
        #pragma unroll
        for (int k = 0; k < NODE_F; k++) out[k] = sB2[k];
        #pragma unroll
        for (int j = 0; j < HID; j++) {
            float hv = fmaxf(h[j], 0.f);
            #pragma unroll
            for (int k = 0; k < NODE_F; k++)
                out[k] = fmaf(hv, sW2n[j * NODE_F + k], out[k]);
        }
        *reinterpret_cast<float4*>(x_out + (size_t)n * NODE_F)     = *reinterpret_cast<float4*>(out);
        *reinterpret_cast<float4*>(x_out + (size_t)n * NODE_F + 4) = *reinterpret_cast<float4*>(out + 4);

        if (FUSE) {   // next-layer p/q from the fresh embedding
            float pv[HID], qv[HID];
            #pragma unroll
            for (int j = 0; j < HID; j++) { pv[j] = 0.f; qv[j] = 0.f; }
            #pragma unroll
            for (int k = 0; k < NODE_F; k++) {
                float v = out[k];
                #pragma unroll
                for (int j = 0; j < HID; j++) {
                    pv[j] = fmaf(v, sA[k * HID + j], pv[j]);
                    qv[j] = fmaf(v, sBm[k * HID + j], qv[j]);
                }
            }
            float4* pd = reinterpret_cast<float4*>(d_p + (size_t)n * HID);
            float4* qd = reinterpret_cast<float4*>(d_q + (size_t)n * HID);
            #pragma unroll
            for (int v = 0; v < 4; v++) {
                pd[v] = reinterpret_cast<float4*>(pv)[v];
                qd[v] = reinterpret_cast<float4*>(qv)[v];
            }
        }
    }

    if (FUSE) {
        int warp = tx >> 5, lane = tx & 31;
        #pragma unroll
        for (int k = 0; k < NODE_F; k++) {
            float s = out[k];
            #pragma unroll
            for (int off = 16; off; off >>= 1)
                s += __shfl_down_sync(0xffffffffu, s, off);
            if (lane == 0) sred[k][warp] = s;
        }
        __syncthreads();
        if (tx < NODE_F) {
            float t = 0.f;
            #pragma unroll
            for (int w = 0; w < 8; w++) t += sred[tx][w];
            atomicAdd(&d_nacc[tx], t);
            __threadfence();
        }
        __syncthreads();
        if (tx == 0) {
            unsigned t = atomicAdd(&d_count, 1u);
            isLast = (t == gridDim.x - 1);
        }
        __syncthreads();

        if (isLast) {
            __threadfence();
            if (tx < 32) {
                float gv = d_g;
                float h = 0.f;
                if (tx < HID) {
                    h = gb1[tx];
                    #pragma unroll
                    for (int i = 0; i < NODE_F; i++)
                        h = fmaf(d_nacc[i] * invN, gW1[i * HID + tx], h);
                    h = fmaf(d_eacc[0] * invE, gW1[8 * HID + tx], h);
                    h = fmaf(d_eacc[1] * invE, gW1[9 * HID + tx], h);
                    h = fmaf(gv, gW1[10 * HID + tx], h);
                    h = fmaxf(h, 0.f) * gW2[tx];
                }
                #pragma unroll
                for (int off = 16; off; off >>= 1)
                    h += __shfl_down_sync(0xffffffffu, h, off);
                float gn = __shfl_sync(0xffffffffu, h, 0) + gb2[0];
                if (tx == 0) d_g = gn;
                if (tx < HID) {
                    ebias_out[tx] = eb1n[tx] + gn * eW1r0n[tx];
                    nbias_out[tx] = nb1n[tx] + gn * nW1r0n[tx];
                }
                if (tx < NODE_F) d_nacc[tx] = 0.f;   // self-clean
                if (tx < EDGE_F) d_eacc[tx] = 0.f;
                if (tx == 0)     d_count = 0u;
            }
        }
    }
}

// ---------------------------------------------------------------------------
extern "C" void kernel_launch(void* const* d_in, const int* in_sizes, int n_in,
                              void* d_out, int out_size)
{
    const float* x0  = (const float*)d_in[0];
    const int*   ei  = (const int*)  d_in[1];
    const float* ea0 = (const float*)d_in[2];
    const float* g0  = (const float*)d_in[3];
    const float* eW1 = (const float*)d_in[4];
    const float* eb1 = (const float*)d_in[5];
    const float* eW2 = (const float*)d_in[6];
    const float* eb2 = (const float*)d_in[7];
    const float* nW1 = (const float*)d_in[8];
    const float* nb1 = (const float*)d_in[9];
    const float* nW2 = (const float*)d_in[10];
    const float* nb2 = (const float*)d_in[11];
    const float* gW1 = (const float*)d_in[12];
    const float* gb1 = (const float*)d_in[13];
    const float* gW2 = (const float*)d_in[14];
    const float* gb2 = (const float*)d_in[15];

    const int N = in_sizes[0] / NODE_F;
    const int E = in_sizes[2] / EDGE_F;
    float* out = (float*)d_out;

    float *xA, *xB, *ea, *pEb, *pNb;
    cudaGetSymbolAddress((void**)&xA,  d_xA);
    cudaGetSymbolAddress((void**)&xB,  d_xB);
    cudaGetSymbolAddress((void**)&ea,  d_ea);
    cudaGetSymbolAddress((void**)&pEb, d_ebias);
    cudaGetSymbolAddress((void**)&pNb, d_nbias);

    const float invE = 1.0f / (float)E;
    const float invN = 1.0f / (float)N;

    const int EW1S = 19 * HID, NW1S = 11 * HID, GW1S = 11 * HID;

    init_kernel<<<1, 32>>>(g0, eW1, eb1, nW1, nb1, pEb, pNb);
    pre_kernel<<<(N + 255) / 256, 256>>>(x0, eW1 + HID, eW1 + 9 * HID, N);

    const float* xin[3]  = {x0, xA, xB};
    float*       xout[3] = {xA, xB, out};
    const float* eain[3] = {ea0, ea, ea};

    const int EPB = 64 * ESTEPS;
    const int eblocks = (E + EPB - 1) / EPB;
    const int nblocks = (N + 255) / 256;

    for (int l = 0; l < 3; l++) {
        const float* C    = eW1 + l * EW1S + 17 * HID;
        const float* W2e  = eW2 + l * HID * EDGE_F;
        const float* b2e  = eb2 + l * EDGE_F;
        const float* eb_l = pEb + (l & 1) * HID;

        if (l < 2)
            edge_kernel<true, true><<<eblocks, 256>>>(ei, eain[l], C, W2e, b2e, eb_l, ea, E);
        else
            edge_kernel<false, false><<<eblocks, 256>>>(ei, eain[l], C, W2e, b2e, eb_l, ea, E);

        const float* W1n  = nW1 + l * NW1S + HID;
        const float* nb_l = pNb + (l & 1) * HID;
        const float* W2n  = nW2 + l * HID * NODE_F;
        const float* b2n  = nb2 + l * NODE_F;

        if (l < 2) {
            node_kernel<true><<<nblocks, 256>>>(
                xin[l], W1n, nb_l, W2n, b2n, xout[l],
                eW1 + (l + 1) * EW1S + HID, eW1 + (l + 1) * EW1S + 9 * HID,
                gW1 + l * GW1S, gb1 + l * HID, gW2 + l * HID, gb2 + l,
                eW1 + (l + 1) * EW1S, eb1 + (l + 1) * HID,
                nW1 + (l + 1) * NW1S, nb1 + (l + 1) * HID,
                pEb + ((l + 1) & 1) * HID, pNb + ((l + 1) & 1) * HID,
                invE, invN, N);
        } else {
            node_kernel<false><<<nblocks, 256>>>(
                xin[l], W1n, nb_l, W2n, b2n, xout[l],
                nullptr, nullptr, nullptr, nullptr, nullptr, nullptr,
                nullptr, nullptr, nullptr, nullptr, nullptr, nullptr,
                invE, invN, N);
        }
    }
}